// round 2
// baseline (speedup 1.0000x reference)
#include <cuda_runtime.h>
#include <math.h>

// Shapes (fixed): B=4, S=2, T=1024, D=512, H=8, HD=64, M = B*S*T = 8192
// rel_err threshold 1e-3; everything fp32 this round.

// ---------------- device workspaces (no allocation allowed) ----------------
__device__ float g_Q[8192ull * 512];      // [m][d]  m = (b*2+s)*1024 + t
__device__ float g_K[8192ull * 512];
__device__ float g_V[8192ull * 512];
__device__ float g_S[67108864ull];        // [ss][b][h][q][k]  2*4*8*1024*1024 (268MB)
__device__ float g_attn[8192ull * 512];   // attention output pre-Wo, m-order
__device__ float g_proj[8192ull * 512];   // after Wo + bias, pre-LN

// ---------------- block reductions ----------------
__device__ __forceinline__ float blk_red_sum(float v, float* sm) {
    int lane = threadIdx.x & 31, wid = threadIdx.x >> 5;
#pragma unroll
    for (int o = 16; o; o >>= 1) v += __shfl_xor_sync(0xffffffffu, v, o);
    if (lane == 0) sm[wid] = v;
    __syncthreads();
    float r = 0.f;
#pragma unroll
    for (int i = 0; i < 8; i++) r += sm[i];
    __syncthreads();
    return r;
}

__device__ __forceinline__ float blk_red_max(float v, float* sm) {
    int lane = threadIdx.x & 31, wid = threadIdx.x >> 5;
#pragma unroll
    for (int o = 16; o; o >>= 1) v = fmaxf(v, __shfl_xor_sync(0xffffffffu, v, o));
    if (lane == 0) sm[wid] = v;
    __syncthreads();
    float r = sm[0];
#pragma unroll
    for (int i = 1; i < 8; i++) r = fmaxf(r, sm[i]);
    __syncthreads();
    return r;
}

// ---------------- 1) QKV projection: C = X(8192x512) @ W^T + b -------------
// NT SGEMM, BM=BN=128, BK=16, 256 threads, 8x8 micro-tile.
// grid = (12, 64): blockIdx.x selects 128-wide slice of the stacked [Wq;Wk;Wv] N=1536.
__global__ __launch_bounds__(256) void k_qkv(
    const float* __restrict__ X,
    const float* __restrict__ Wq, const float* __restrict__ bq,
    const float* __restrict__ Wk, const float* __restrict__ bk,
    const float* __restrict__ Wv, const float* __restrict__ bv)
{
    const int n0g = blockIdx.x * 128;
    const int m0  = blockIdx.y * 128;
    const int mat = n0g >> 9;          // 0:Q 1:K 2:V (128 | 512, so never straddles)
    const int n0  = n0g & 511;
    const float* W    = (mat == 0) ? Wq : (mat == 1) ? Wk : Wv;
    const float* bias = (mat == 0) ? bq : (mat == 1) ? bk : bv;
    float*       C    = (mat == 0) ? g_Q : (mat == 1) ? g_K : g_V;

    __shared__ float As[16][132];
    __shared__ float Bs[16][132];
    const int tid = threadIdx.x;
    const int tm = tid >> 4, tn = tid & 15;
    float acc[8][8] = {};

    for (int k0 = 0; k0 < 512; k0 += 16) {
#pragma unroll
        for (int i = 0; i < 2; i++) {
            int j = tid + 256 * i;                 // 0..511 float4 slots
            int row = j >> 2, c4 = (j & 3) * 4;
            float4 va = *(const float4*)(X + (size_t)(m0 + row) * 512 + k0 + c4);
            As[c4 + 0][row] = va.x; As[c4 + 1][row] = va.y;
            As[c4 + 2][row] = va.z; As[c4 + 3][row] = va.w;
            float4 vb = *(const float4*)(W + (size_t)(n0 + row) * 512 + k0 + c4);
            Bs[c4 + 0][row] = vb.x; Bs[c4 + 1][row] = vb.y;
            Bs[c4 + 2][row] = vb.z; Bs[c4 + 3][row] = vb.w;
        }
        __syncthreads();
#pragma unroll
        for (int kk = 0; kk < 16; kk++) {
            float a[8], b[8];
#pragma unroll
            for (int i = 0; i < 8; i++) { a[i] = As[kk][tm * 8 + i]; b[i] = Bs[kk][tn * 8 + i]; }
#pragma unroll
            for (int i = 0; i < 8; i++)
#pragma unroll
                for (int j = 0; j < 8; j++) acc[i][j] += a[i] * b[j];
        }
        __syncthreads();
    }
#pragma unroll
    for (int i = 0; i < 8; i++) {
        int m = m0 + tm * 8 + i;
#pragma unroll
        for (int j = 0; j < 8; j++) {
            int n = n0 + tn * 8 + j;
            C[(size_t)m * 512 + n] = acc[i][j] + bias[n];
        }
    }
}

// ---------------- 2) scores: L[ss] = Q_ss @ K_{1-ss}^T * scale -------------
// Batched NT SGEMM per (ss,b,h): M=N=1024, K=64 (lda=ldb=512 strided head view).
// grid = (8, 8, 64)  z = ss*32 + b*8 + h
__global__ __launch_bounds__(256) void k_scores()
{
    const int z = blockIdx.z;
    const int ss = z >> 5, bh = z & 31, b = bh >> 3, h = bh & 7;
    const float* A  = g_Q + ((size_t)(b * 2 + ss) * 1024) * 512 + h * 64;
    const float* Bp = g_K + ((size_t)(b * 2 + (1 - ss)) * 1024) * 512 + h * 64;
    float* C = g_S + ((size_t)(ss * 32 + bh) << 20);

    const int n0 = blockIdx.x * 128;
    const int m0 = blockIdx.y * 128;

    __shared__ float As[16][132];
    __shared__ float Bs[16][132];
    const int tid = threadIdx.x;
    const int tm = tid >> 4, tn = tid & 15;
    float acc[8][8] = {};

    for (int k0 = 0; k0 < 64; k0 += 16) {
#pragma unroll
        for (int i = 0; i < 2; i++) {
            int j = tid + 256 * i;
            int row = j >> 2, c4 = (j & 3) * 4;
            float4 va = *(const float4*)(A + (size_t)(m0 + row) * 512 + k0 + c4);
            As[c4 + 0][row] = va.x; As[c4 + 1][row] = va.y;
            As[c4 + 2][row] = va.z; As[c4 + 3][row] = va.w;
            float4 vb = *(const float4*)(Bp + (size_t)(n0 + row) * 512 + k0 + c4);
            Bs[c4 + 0][row] = vb.x; Bs[c4 + 1][row] = vb.y;
            Bs[c4 + 2][row] = vb.z; Bs[c4 + 3][row] = vb.w;
        }
        __syncthreads();
#pragma unroll
        for (int kk = 0; kk < 16; kk++) {
            float a[8], bb[8];
#pragma unroll
            for (int i = 0; i < 8; i++) { a[i] = As[kk][tm * 8 + i]; bb[i] = Bs[kk][tn * 8 + i]; }
#pragma unroll
            for (int i = 0; i < 8; i++)
#pragma unroll
                for (int j = 0; j < 8; j++) acc[i][j] += a[i] * bb[j];
        }
        __syncthreads();
    }
#pragma unroll
    for (int i = 0; i < 8; i++) {
        size_t m = m0 + tm * 8 + i;
#pragma unroll
        for (int j = 0; j < 8; j++) {
            C[m * 1024 + n0 + tn * 8 + j] = acc[i][j] * 0.125f;  // 1/sqrt(64)
        }
    }
}

// ---------------- 3) softmax + competitive combine (in place) --------------
// One block per (b,h,q) row pair. grid = 32768.
__global__ __launch_bounds__(256) void k_combine()
{
    const size_t row = blockIdx.x;           // bh*1024 + q
    float* p1 = g_S + row * 1024;
    float* p2 = g_S + 33554432ull + row * 1024;
    const int tid = threadIdx.x;
    __shared__ float sm[8];

    float l1[4], l2[4];
#pragma unroll
    for (int i = 0; i < 4; i++) { l1[i] = p1[tid + 256 * i]; l2[i] = p2[tid + 256 * i]; }

    float m1 = -1e30f, m2 = -1e30f;
#pragma unroll
    for (int i = 0; i < 4; i++) { m1 = fmaxf(m1, l1[i]); m2 = fmaxf(m2, l2[i]); }
    m1 = blk_red_max(m1, sm);
    m2 = blk_red_max(m2, sm);

    float z1 = 0.f, z2 = 0.f;
#pragma unroll
    for (int i = 0; i < 4; i++) {
        l1[i] = __expf(l1[i] - m1); z1 += l1[i];
        l2[i] = __expf(l2[i] - m2); z2 += l2[i];
    }
    z1 = blk_red_sum(z1, sm);
    z2 = blk_red_sum(z2, sm);
    const float i1 = 1.f / z1, i2 = 1.f / z2;

#pragma unroll
    for (int i = 0; i < 4; i++) {
        float s12 = l1[i] * i1;
        float s21 = l2[i] * i2;
        float inv = 1.f / (s12 + s21 + 1e-6f);
        p1[tid + 256 * i] = s12 * inv;
        p2[tid + 256 * i] = s21 * inv;
    }
}

// ---------------- 4) AV: H_ss = A_ss(1024x1024) @ V_{1-ss}(1024x64) --------
// NN SGEMM, BM=128, BN=64, BK=16, 256 threads, 8x4 micro-tile.
// grid = (8, 64)  y = ss*32 + b*8 + h
__global__ __launch_bounds__(256) void k_av()
{
    const int z = blockIdx.y;
    const int ss = z >> 5, bh = z & 31, b = bh >> 3, h = bh & 7;
    const float* A  = g_S + ((size_t)(ss * 32 + bh) << 20);
    const float* Vp = g_V + ((size_t)(b * 2 + (1 - ss)) * 1024) * 512 + h * 64;
    float* C = g_attn + ((size_t)(b * 2 + ss) * 1024) * 512 + h * 64;
    const int m0 = blockIdx.x * 128;

    __shared__ float  As[16][132];
    __shared__ float4 Bs4[16][16];
    const int tid = threadIdx.x;
    const int tm = tid >> 4, tn = tid & 15;
    float acc[8][4] = {};

    for (int k0 = 0; k0 < 1024; k0 += 16) {
#pragma unroll
        for (int i = 0; i < 2; i++) {
            int j = tid + 256 * i;
            int row = j >> 2, c4 = (j & 3) * 4;
            float4 va = *(const float4*)(A + (size_t)(m0 + row) * 1024 + k0 + c4);
            As[c4 + 0][row] = va.x; As[c4 + 1][row] = va.y;
            As[c4 + 2][row] = va.z; As[c4 + 3][row] = va.w;
        }
        {
            int row = tid >> 4, c4 = tid & 15;
            Bs4[row][c4] = *(const float4*)(Vp + (size_t)(k0 + row) * 512 + c4 * 4);
        }
        __syncthreads();
#pragma unroll
        for (int kk = 0; kk < 16; kk++) {
            float a[8];
#pragma unroll
            for (int i = 0; i < 8; i++) a[i] = As[kk][tm * 8 + i];
            float4 bv = Bs4[kk][tn];
#pragma unroll
            for (int i = 0; i < 8; i++) {
                acc[i][0] += a[i] * bv.x;
                acc[i][1] += a[i] * bv.y;
                acc[i][2] += a[i] * bv.z;
                acc[i][3] += a[i] * bv.w;
            }
        }
        __syncthreads();
    }
#pragma unroll
    for (int i = 0; i < 8; i++) {
        float4 o = make_float4(acc[i][0], acc[i][1], acc[i][2], acc[i][3]);
        *(float4*)(C + (size_t)(m0 + tm * 8 + i) * 512 + tn * 4) = o;
    }
}

// ---------------- 5) output projection: g_proj = g_attn @ Wo^T + bo --------
// grid = (4, 64)
__global__ __launch_bounds__(256) void k_out(const float* __restrict__ Wo,
                                             const float* __restrict__ bo)
{
    const int n0 = blockIdx.x * 128;
    const int m0 = blockIdx.y * 128;
    __shared__ float As[16][132];
    __shared__ float Bs[16][132];
    const int tid = threadIdx.x;
    const int tm = tid >> 4, tn = tid & 15;
    float acc[8][8] = {};

    for (int k0 = 0; k0 < 512; k0 += 16) {
#pragma unroll
        for (int i = 0; i < 2; i++) {
            int j = tid + 256 * i;
            int row = j >> 2, c4 = (j & 3) * 4;
            float4 va = *(const float4*)(g_attn + (size_t)(m0 + row) * 512 + k0 + c4);
            As[c4 + 0][row] = va.x; As[c4 + 1][row] = va.y;
            As[c4 + 2][row] = va.z; As[c4 + 3][row] = va.w;
            float4 vb = *(const float4*)(Wo + (size_t)(n0 + row) * 512 + k0 + c4);
            Bs[c4 + 0][row] = vb.x; Bs[c4 + 1][row] = vb.y;
            Bs[c4 + 2][row] = vb.z; Bs[c4 + 3][row] = vb.w;
        }
        __syncthreads();
#pragma unroll
        for (int kk = 0; kk < 16; kk++) {
            float a[8], b[8];
#pragma unroll
            for (int i = 0; i < 8; i++) { a[i] = As[kk][tm * 8 + i]; b[i] = Bs[kk][tn * 8 + i]; }
#pragma unroll
            for (int i = 0; i < 8; i++)
#pragma unroll
                for (int j = 0; j < 8; j++) acc[i][j] += a[i] * b[j];
        }
        __syncthreads();
    }
#pragma unroll
    for (int i = 0; i < 8; i++) {
        int m = m0 + tm * 8 + i;
#pragma unroll
        for (int j = 0; j < 8; j++) {
            int n = n0 + tn * 8 + j;
            g_proj[(size_t)m * 512 + n] = acc[i][j] + bo[n];
        }
    }
}

// ---------------- 6) LayerNorm + gate + residual ---------------------------
// One block per row (8192). var computed as E[x^2]-mu^2 (fp32 OK at these scales).
__global__ __launch_bounds__(256) void k_ln(
    const float* __restrict__ hidden,
    const float* __restrict__ ln_g, const float* __restrict__ ln_b,
    const float* __restrict__ alpha, float* __restrict__ out)
{
    const int m = blockIdx.x;
    const int s = (m >> 10) & 1;
    const float* p = g_proj + (size_t)m * 512;
    const int tid = threadIdx.x;
    __shared__ float sm[8];

    float x0 = p[tid], x1 = p[tid + 256];
    float sum = blk_red_sum(x0 + x1, sm);
    float sq  = blk_red_sum(x0 * x0 + x1 * x1, sm);
    float mu  = sum * (1.f / 512.f);
    float var = sq * (1.f / 512.f) - mu * mu;
    float rstd = rsqrtf(var + 1e-5f);
    float al = alpha[s];
    size_t base = (size_t)m * 512;

    {
        int e = tid;
        float y = (x0 - mu) * rstd * ln_g[s * 512 + e] + ln_b[s * 512 + e];
        out[base + e] = hidden[base + e] + y * al;
    }
    {
        int e = tid + 256;
        float y = (x1 - mu) * rstd * ln_g[s * 512 + e] + ln_b[s * 512 + e];
        out[base + e] = hidden[base + e] + y * al;
    }
}

// ---------------- launch ---------------------------------------------------
extern "C" void kernel_launch(void* const* d_in, const int* in_sizes, int n_in,
                              void* d_out, int out_size)
{
    const float* hidden = (const float*)d_in[0];
    const float* Wq = (const float*)d_in[1];  const float* bq = (const float*)d_in[2];
    const float* Wk = (const float*)d_in[3];  const float* bk = (const float*)d_in[4];
    const float* Wv = (const float*)d_in[5];  const float* bv = (const float*)d_in[6];
    const float* Wo = (const float*)d_in[7];  const float* bo = (const float*)d_in[8];
    const float* lng = (const float*)d_in[9]; const float* lnb = (const float*)d_in[10];
    const float* alpha = (const float*)d_in[11];
    float* out = (float*)d_out;

    k_qkv<<<dim3(12, 64), 256>>>(hidden, Wq, bq, Wk, bk, Wv, bv);
    k_scores<<<dim3(8, 8, 64), 256>>>();
    k_combine<<<32768, 256>>>();
    k_av<<<dim3(8, 64), 256>>>();
    k_out<<<dim3(4, 64), 256>>>(Wo, bo);
    k_ln<<<8192, 256>>>(hidden, lng, lnb, alpha, out);
}

// round 5
// speedup vs baseline: 3.0114x; 3.0114x over previous
#include <cuda_runtime.h>
#include <cuda_bf16.h>
#include <stdint.h>
#include <math.h>

// Shapes (fixed): B=4, S=2, T=1024, D=512, H=8, HD=64, M = B*S*T = 8192
// bf16 tensor-core GEMMs (mma.sync m16n8k16, fp32 accum); softmax/combine/LN fp32.

// ---------------- device workspaces ----------------
__device__ __nv_bfloat16 g_Xh[8192ull * 512];     // hidden in bf16
__device__ __nv_bfloat16 g_Wh[4ull * 512 * 512];  // [Wq;Wk;Wv;Wo] bf16, row-major [out][in]
__device__ __nv_bfloat16 g_Qh[8192ull * 512];     // Q*0.125 (scale folded)
__device__ __nv_bfloat16 g_Kh[8192ull * 512];
__device__ __nv_bfloat16 g_Vh[8192ull * 512];
__device__ __nv_bfloat16 g_S[67108864ull];        // [ss][b][h][q][k] logits -> probs (in place)
__device__ __nv_bfloat16 g_attnh[8192ull * 512];  // attention out pre-Wo
__device__ float         g_proj[8192ull * 512];   // after Wo + bias, pre-LN

// ---------------- helpers ----------------
__device__ __forceinline__ uint32_t pack_bf16x2(float a, float b) {
    __nv_bfloat162 h = __floats2bfloat162_rn(a, b);   // .x = a (low), .y = b (high)
    return *reinterpret_cast<uint32_t*>(&h);
}

__device__ __forceinline__ void mma16816(float* c, const uint32_t* a, uint32_t b0, uint32_t b1) {
    asm volatile(
        "mma.sync.aligned.m16n8k16.row.col.f32.bf16.bf16.f32 "
        "{%0,%1,%2,%3}, {%4,%5,%6,%7}, {%8,%9}, {%0,%1,%2,%3};\n"
        : "+f"(c[0]), "+f"(c[1]), "+f"(c[2]), "+f"(c[3])
        : "r"(a[0]), "r"(a[1]), "r"(a[2]), "r"(a[3]), "r"(b0), "r"(b1));
}

__device__ __forceinline__ float blk_red_sum(float v, float* sm) {
    int lane = threadIdx.x & 31, wid = threadIdx.x >> 5;
#pragma unroll
    for (int o = 16; o; o >>= 1) v += __shfl_xor_sync(0xffffffffu, v, o);
    if (lane == 0) sm[wid] = v;
    __syncthreads();
    float r = 0.f;
#pragma unroll
    for (int i = 0; i < 8; i++) r += sm[i];
    __syncthreads();
    return r;
}

__device__ __forceinline__ float blk_red_max(float v, float* sm) {
    int lane = threadIdx.x & 31, wid = threadIdx.x >> 5;
#pragma unroll
    for (int o = 16; o; o >>= 1) v = fmaxf(v, __shfl_xor_sync(0xffffffffu, v, o));
    if (lane == 0) sm[wid] = v;
    __syncthreads();
    float r = sm[0];
#pragma unroll
    for (int i = 1; i < 8; i++) r = fmaxf(r, sm[i]);
    __syncthreads();
    return r;
}

// ---------------- 0) convert inputs to bf16 ----------------
// jobs over float4: 1048576 (X) + 262144 (4 weight matrices) = 1310720
__global__ __launch_bounds__(256) void k_prep(
    const float* __restrict__ X,
    const float* __restrict__ Wq, const float* __restrict__ Wk,
    const float* __restrict__ Wv, const float* __restrict__ Wo)
{
    const int idx = blockIdx.x * 256 + threadIdx.x;
    if (idx < 1048576) {
        float4 v = ((const float4*)X)[idx];
        uint2 o; o.x = pack_bf16x2(v.x, v.y); o.y = pack_bf16x2(v.z, v.w);
        ((uint2*)g_Xh)[idx] = o;
    } else {
        int j = idx - 1048576;             // 0..262143 (65536 float4 per matrix)
        int w = j >> 16;
        const float4* src = (w == 0) ? (const float4*)Wq : (w == 1) ? (const float4*)Wk
                          : (w == 2) ? (const float4*)Wv : (const float4*)Wo;
        float4 v = src[j & 65535];
        uint2 o; o.x = pack_bf16x2(v.x, v.y); o.y = pack_bf16x2(v.z, v.w);
        ((uint2*)g_Wh)[j] = o;
    }
}

// ---------------- 1) QKV projection (bf16 mma) ----------------
// C = X(8192x512) @ W^T + b. grid (12, 64), 128 threads, BM=BN=128, BK=32, warp 64x64.
__global__ __launch_bounds__(128) void k_qkv_mma(
    const float* __restrict__ bq, const float* __restrict__ bk, const float* __restrict__ bv)
{
    __shared__ __nv_bfloat16 As[128][40];
    __shared__ __nv_bfloat16 Bs[128][40];
    const int tid = threadIdx.x, lane = tid & 31, warp = tid >> 5;
    const int wm = warp >> 1, wn = warp & 1;
    const int g = lane >> 2, t = lane & 3;
    const int m0 = blockIdx.y * 128, n0g = blockIdx.x * 128;

    float acc[4][8][4] = {};

    for (int k0 = 0; k0 < 512; k0 += 32) {
        {
            const __nv_bfloat16* srcA = g_Xh + (size_t)(m0 + tid) * 512 + k0;
            const __nv_bfloat16* srcB = g_Wh + (size_t)(n0g + tid) * 512 + k0;
#pragma unroll
            for (int c = 0; c < 4; c++) {
                *(uint4*)&As[tid][c * 8] = *(const uint4*)(srcA + c * 8);
                *(uint4*)&Bs[tid][c * 8] = *(const uint4*)(srcB + c * 8);
            }
        }
        __syncthreads();
#pragma unroll
        for (int kk = 0; kk < 32; kk += 16) {
            uint32_t a[4][4];
#pragma unroll
            for (int mi = 0; mi < 4; mi++)
#pragma unroll
                for (int p = 0; p < 4; p++)
                    a[mi][p] = *(const uint32_t*)&As[wm * 64 + mi * 16 + ((p & 1) << 3) + g]
                                                   [kk + 2 * t + ((p >> 1) << 3)];
#pragma unroll
            for (int ni = 0; ni < 8; ni++) {
                uint32_t b0 = *(const uint32_t*)&Bs[wn * 64 + ni * 8 + g][kk + 2 * t];
                uint32_t b1 = *(const uint32_t*)&Bs[wn * 64 + ni * 8 + g][kk + 2 * t + 8];
#pragma unroll
                for (int mi = 0; mi < 4; mi++) mma16816(acc[mi][ni], a[mi], b0, b1);
            }
        }
        __syncthreads();
    }

    const int mat = n0g >> 9, nloc = n0g & 511;
    const float* bias = (mat == 0) ? bq : (mat == 1) ? bk : bv;
    __nv_bfloat16* out = (mat == 0) ? g_Qh : (mat == 1) ? g_Kh : g_Vh;
    const float scale = (mat == 0) ? 0.125f : 1.0f;   // fold 1/sqrt(HD) into Q

#pragma unroll
    for (int mi = 0; mi < 4; mi++) {
        int r0 = m0 + wm * 64 + mi * 16 + g;
#pragma unroll
        for (int ni = 0; ni < 8; ni++) {
            int col = nloc + wn * 64 + ni * 8 + 2 * t;
            float b0f = bias[col], b1f = bias[col + 1];
            *(uint32_t*)(out + (size_t)r0 * 512 + col) =
                pack_bf16x2((acc[mi][ni][0] + b0f) * scale, (acc[mi][ni][1] + b1f) * scale);
            *(uint32_t*)(out + (size_t)(r0 + 8) * 512 + col) =
                pack_bf16x2((acc[mi][ni][2] + b0f) * scale, (acc[mi][ni][3] + b1f) * scale);
        }
    }
}

// ---------------- 2) scores: L[ss] = Qs_ss @ K_{1-ss}^T (bf16 mma) ----------------
// grid (8, 8, 64): z = ss*32 + b*8 + h. M=N=1024, K=64. Output bf16 logits to g_S.
__global__ __launch_bounds__(128) void k_scores_mma()
{
    __shared__ __nv_bfloat16 As[128][40];
    __shared__ __nv_bfloat16 Bs[128][40];
    const int z = blockIdx.z;
    const int ss = z >> 5, bh = z & 31, b = bh >> 3, h = bh & 7;
    const __nv_bfloat16* Abase = g_Qh + ((size_t)(b * 2 + ss) * 1024) * 512 + h * 64;
    const __nv_bfloat16* Bbase = g_Kh + ((size_t)(b * 2 + (1 - ss)) * 1024) * 512 + h * 64;
    __nv_bfloat16* C = g_S + ((size_t)(ss * 32 + bh) << 20);

    const int tid = threadIdx.x, lane = tid & 31, warp = tid >> 5;
    const int wm = warp >> 1, wn = warp & 1;
    const int g = lane >> 2, t = lane & 3;
    const int m0 = blockIdx.y * 128, n0 = blockIdx.x * 128;

    float acc[4][8][4] = {};

    for (int k0 = 0; k0 < 64; k0 += 32) {
        {
            const __nv_bfloat16* srcA = Abase + (size_t)(m0 + tid) * 512 + k0;
            const __nv_bfloat16* srcB = Bbase + (size_t)(n0 + tid) * 512 + k0;
#pragma unroll
            for (int c = 0; c < 4; c++) {
                *(uint4*)&As[tid][c * 8] = *(const uint4*)(srcA + c * 8);
                *(uint4*)&Bs[tid][c * 8] = *(const uint4*)(srcB + c * 8);
            }
        }
        __syncthreads();
#pragma unroll
        for (int kk = 0; kk < 32; kk += 16) {
            uint32_t a[4][4];
#pragma unroll
            for (int mi = 0; mi < 4; mi++)
#pragma unroll
                for (int p = 0; p < 4; p++)
                    a[mi][p] = *(const uint32_t*)&As[wm * 64 + mi * 16 + ((p & 1) << 3) + g]
                                                   [kk + 2 * t + ((p >> 1) << 3)];
#pragma unroll
            for (int ni = 0; ni < 8; ni++) {
                uint32_t b0 = *(const uint32_t*)&Bs[wn * 64 + ni * 8 + g][kk + 2 * t];
                uint32_t b1 = *(const uint32_t*)&Bs[wn * 64 + ni * 8 + g][kk + 2 * t + 8];
#pragma unroll
                for (int mi = 0; mi < 4; mi++) mma16816(acc[mi][ni], a[mi], b0, b1);
            }
        }
        __syncthreads();
    }

#pragma unroll
    for (int mi = 0; mi < 4; mi++) {
        size_t r0 = m0 + wm * 64 + mi * 16 + g;
#pragma unroll
        for (int ni = 0; ni < 8; ni++) {
            int col = n0 + wn * 64 + ni * 8 + 2 * t;
            *(uint32_t*)(C + r0 * 1024 + col) = pack_bf16x2(acc[mi][ni][0], acc[mi][ni][1]);
            *(uint32_t*)(C + (r0 + 8) * 1024 + col) = pack_bf16x2(acc[mi][ni][2], acc[mi][ni][3]);
        }
    }
}

// ---------------- 3) softmax + competitive combine (bf16 in-place) ----------------
__global__ __launch_bounds__(256) void k_combine()
{
    const size_t row = blockIdx.x;                 // bh*1024 + q
    __nv_bfloat16* p1 = g_S + row * 1024;
    __nv_bfloat16* p2 = g_S + 33554432ull + row * 1024;
    const int tid = threadIdx.x;
    __shared__ float sm[8];

    float l1[4], l2[4];
    {
        uint2 u1 = *(const uint2*)(p1 + 4 * tid);
        uint2 u2 = *(const uint2*)(p2 + 4 * tid);
        const __nv_bfloat16* b1p = (const __nv_bfloat16*)&u1;
        const __nv_bfloat16* b2p = (const __nv_bfloat16*)&u2;
#pragma unroll
        for (int i = 0; i < 4; i++) { l1[i] = __bfloat162float(b1p[i]); l2[i] = __bfloat162float(b2p[i]); }
    }

    float m1 = -1e30f, m2 = -1e30f;
#pragma unroll
    for (int i = 0; i < 4; i++) { m1 = fmaxf(m1, l1[i]); m2 = fmaxf(m2, l2[i]); }
    m1 = blk_red_max(m1, sm);
    m2 = blk_red_max(m2, sm);

    float z1 = 0.f, z2 = 0.f;
#pragma unroll
    for (int i = 0; i < 4; i++) {
        l1[i] = __expf(l1[i] - m1); z1 += l1[i];
        l2[i] = __expf(l2[i] - m2); z2 += l2[i];
    }
    z1 = blk_red_sum(z1, sm);
    z2 = blk_red_sum(z2, sm);
    const float i1 = 1.f / z1, i2 = 1.f / z2;

    uint2 o1, o2;
    float v1[4], v2[4];
#pragma unroll
    for (int i = 0; i < 4; i++) {
        float s12 = l1[i] * i1, s21 = l2[i] * i2;
        float inv = 1.f / (s12 + s21 + 1e-6f);
        v1[i] = s12 * inv; v2[i] = s21 * inv;
    }
    o1.x = pack_bf16x2(v1[0], v1[1]); o1.y = pack_bf16x2(v1[2], v1[3]);
    o2.x = pack_bf16x2(v2[0], v2[1]); o2.y = pack_bf16x2(v2[2], v2[3]);
    *(uint2*)(p1 + 4 * tid) = o1;
    *(uint2*)(p2 + 4 * tid) = o2;
}

// ---------------- 4) AV: H_ss = A_ss(1024x1024) @ V_{1-ss}(1024x64) ----------------
// grid (8, 64). BM=128, BN=64, BK=32, warp tile 64x32 (2x2 warps).
__global__ __launch_bounds__(128) void k_av_mma()
{
    __shared__ __nv_bfloat16 As[128][40];
    __shared__ __nv_bfloat16 Vs[64][40];           // [dim][token] (transposed tile)
    const int z = blockIdx.y;
    const int ss = z >> 5, bh = z & 31, b = bh >> 3, h = bh & 7;
    const __nv_bfloat16* Abase = g_S + ((size_t)(ss * 32 + bh) << 20);
    const __nv_bfloat16* Vbase = g_Vh + ((size_t)(b * 2 + (1 - ss)) * 1024) * 512 + h * 64;
    __nv_bfloat16* Cbase = g_attnh + ((size_t)(b * 2 + ss) * 1024) * 512 + h * 64;

    const int tid = threadIdx.x, lane = tid & 31, warp = tid >> 5;
    const int wm = warp >> 1, wn = warp & 1;
    const int g = lane >> 2, t = lane & 3;
    const int m0 = blockIdx.x * 128;

    float acc[4][4][4] = {};

    for (int k0 = 0; k0 < 1024; k0 += 32) {
        {   // A tile [128][32]
            const __nv_bfloat16* srcA = Abase + (size_t)(m0 + tid) * 1024 + k0;
#pragma unroll
            for (int c = 0; c < 4; c++) *(uint4*)&As[tid][c * 8] = *(const uint4*)(srcA + c * 8);
        }
        {   // V tile [32 tok][64 dim] -> Vs[dim][tok]
            int kr = tid >> 2, dseg = (tid & 3) * 16;
            const __nv_bfloat16* src = Vbase + (size_t)(k0 + kr) * 512 + dseg;
            __nv_bfloat16 tmp[16];
            *(uint4*)tmp = *(const uint4*)src;
            *(uint4*)(tmp + 8) = *(const uint4*)(src + 8);
#pragma unroll
            for (int j = 0; j < 16; j++) Vs[dseg + j][kr] = tmp[j];
        }
        __syncthreads();
#pragma unroll
        for (int kk = 0; kk < 32; kk += 16) {
            uint32_t a[4][4];
#pragma unroll
            for (int mi = 0; mi < 4; mi++)
#pragma unroll
                for (int p = 0; p < 4; p++)
                    a[mi][p] = *(const uint32_t*)&As[wm * 64 + mi * 16 + ((p & 1) << 3) + g]
                                                   [kk + 2 * t + ((p >> 1) << 3)];
#pragma unroll
            for (int ni = 0; ni < 4; ni++) {
                uint32_t b0 = *(const uint32_t*)&Vs[wn * 32 + ni * 8 + g][kk + 2 * t];
                uint32_t b1 = *(const uint32_t*)&Vs[wn * 32 + ni * 8 + g][kk + 2 * t + 8];
#pragma unroll
                for (int mi = 0; mi < 4; mi++) mma16816(acc[mi][ni], a[mi], b0, b1);
            }
        }
        __syncthreads();
    }

#pragma unroll
    for (int mi = 0; mi < 4; mi++) {
        int r0 = m0 + wm * 64 + mi * 16 + g;
#pragma unroll
        for (int ni = 0; ni < 4; ni++) {
            int col = wn * 32 + ni * 8 + 2 * t;
            *(uint32_t*)(Cbase + (size_t)r0 * 512 + col) = pack_bf16x2(acc[mi][ni][0], acc[mi][ni][1]);
            *(uint32_t*)(Cbase + (size_t)(r0 + 8) * 512 + col) = pack_bf16x2(acc[mi][ni][2], acc[mi][ni][3]);
        }
    }
}

// ---------------- 5) output projection: g_proj = attn @ Wo^T + bo (fp32 out) ----------------
// grid (4, 64)
__global__ __launch_bounds__(128) void k_out_mma(const float* __restrict__ bo)
{
    __shared__ __nv_bfloat16 As[128][40];
    __shared__ __nv_bfloat16 Bs[128][40];
    const int tid = threadIdx.x, lane = tid & 31, warp = tid >> 5;
    const int wm = warp >> 1, wn = warp & 1;
    const int g = lane >> 2, t = lane & 3;
    const int m0 = blockIdx.y * 128, n0 = blockIdx.x * 128;
    const __nv_bfloat16* Wo = g_Wh + 3ull * 512 * 512;

    float acc[4][8][4] = {};

    for (int k0 = 0; k0 < 512; k0 += 32) {
        {
            const __nv_bfloat16* srcA = g_attnh + (size_t)(m0 + tid) * 512 + k0;
            const __nv_bfloat16* srcB = Wo + (size_t)(n0 + tid) * 512 + k0;
#pragma unroll
            for (int c = 0; c < 4; c++) {
                *(uint4*)&As[tid][c * 8] = *(const uint4*)(srcA + c * 8);
                *(uint4*)&Bs[tid][c * 8] = *(const uint4*)(srcB + c * 8);
            }
        }
        __syncthreads();
#pragma unroll
        for (int kk = 0; kk < 32; kk += 16) {
            uint32_t a[4][4];
#pragma unroll
            for (int mi = 0; mi < 4; mi++)
#pragma unroll
                for (int p = 0; p < 4; p++)
                    a[mi][p] = *(const uint32_t*)&As[wm * 64 + mi * 16 + ((p & 1) << 3) + g]
                                                   [kk + 2 * t + ((p >> 1) << 3)];
#pragma unroll
            for (int ni = 0; ni < 8; ni++) {
                uint32_t b0 = *(const uint32_t*)&Bs[wn * 64 + ni * 8 + g][kk + 2 * t];
                uint32_t b1 = *(const uint32_t*)&Bs[wn * 64 + ni * 8 + g][kk + 2 * t + 8];
#pragma unroll
                for (int mi = 0; mi < 4; mi++) mma16816(acc[mi][ni], a[mi], b0, b1);
            }
        }
        __syncthreads();
    }

#pragma unroll
    for (int mi = 0; mi < 4; mi++) {
        int r0 = m0 + wm * 64 + mi * 16 + g;
#pragma unroll
        for (int ni = 0; ni < 8; ni++) {
            int col = n0 + wn * 64 + ni * 8 + 2 * t;
            float b0f = bo[col], b1f = bo[col + 1];
            float2 lo = make_float2(acc[mi][ni][0] + b0f, acc[mi][ni][1] + b1f);
            float2 hi = make_float2(acc[mi][ni][2] + b0f, acc[mi][ni][3] + b1f);
            *(float2*)(g_proj + (size_t)r0 * 512 + col) = lo;
            *(float2*)(g_proj + (size_t)(r0 + 8) * 512 + col) = hi;
        }
    }
}

// ---------------- 6) LayerNorm + gate + residual ----------------
__global__ __launch_bounds__(256) void k_ln(
    const float* __restrict__ hidden,
    const float* __restrict__ ln_g, const float* __restrict__ ln_b,
    const float* __restrict__ alpha, float* __restrict__ out)
{
    const int m = blockIdx.x;
    const int s = (m >> 10) & 1;
    const float* p = g_proj + (size_t)m * 512;
    const int tid = threadIdx.x;
    __shared__ float sm[8];

    float x0 = p[tid], x1 = p[tid + 256];
    float sum = blk_red_sum(x0 + x1, sm);
    float sq  = blk_red_sum(x0 * x0 + x1 * x1, sm);
    float mu  = sum * (1.f / 512.f);
    float var = sq * (1.f / 512.f) - mu * mu;
    float rstd = rsqrtf(var + 1e-5f);
    float al = alpha[s];
    size_t base = (size_t)m * 512;

    {
        int e = tid;
        float y = (x0 - mu) * rstd * ln_g[s * 512 + e] + ln_b[s * 512 + e];
        out[base + e] = hidden[base + e] + y * al;
    }
    {
        int e = tid + 256;
        float y = (x1 - mu) * rstd * ln_g[s * 512 + e] + ln_b[s * 512 + e];
        out[base + e] = hidden[base + e] + y * al;
    }
}

// ---------------- launch ----------------
extern "C" void kernel_launch(void* const* d_in, const int* in_sizes, int n_in,
                              void* d_out, int out_size)
{
    const float* hidden = (const float*)d_in[0];
    const float* Wq = (const float*)d_in[1];  const float* bq = (const float*)d_in[2];
    const float* Wk = (const float*)d_in[3];  const float* bk = (const float*)d_in[4];
    const float* Wv = (const float*)d_in[5];  const float* bv = (const float*)d_in[6];
    const float* Wo = (const float*)d_in[7];  const float* bo = (const float*)d_in[8];
    const float* lng = (const float*)d_in[9]; const float* lnb = (const float*)d_in[10];
    const float* alpha = (const float*)d_in[11];
    float* out = (float*)d_out;

    k_prep<<<5120, 256>>>(hidden, Wq, Wk, Wv, Wo);
    k_qkv_mma<<<dim3(12, 64), 128>>>(bq, bk, bv);
    k_scores_mma<<<dim3(8, 8, 64), 128>>>();
    k_combine<<<32768, 256>>>();
    k_av_mma<<<dim3(8, 64), 128>>>();
    k_out_mma<<<dim3(4, 64), 128>>>(bo);
    k_ln<<<8192, 256>>>(hidden, lng, lnb, alpha, out);
}